// round 11
// baseline (speedup 1.0000x reference)
#include <cuda_runtime.h>
#include <cuda_bf16.h>

#define T_STEPS  2048
#define BATCH    4096
#define INSZ     8
#define HID      20
#define G4       80
#define GROUPS   3       // thread groups per CTA
#define NGE      6       // batch elems per CTA (2 per thread group)
#define NTHREADS 64      // 2 warps; 60 active lanes
#define ROWW     24      // padded smem row (floats): h[0:20], pad (96B, 16B-aligned)

typedef unsigned long long u64;

__device__ __forceinline__ u64 fma2(u64 a, u64 b, u64 c) {
    u64 d;
    asm("fma.rn.f32x2 %0, %1, %2, %3;" : "=l"(d) : "l"(a), "l"(b), "l"(c));
    return d;
}
__device__ __forceinline__ u64 pack2(float lo, float hi) {
    u64 d;
    asm("mov.b64 %0, {%1, %2};" : "=l"(d) : "f"(lo), "f"(hi));
    return d;
}
__device__ __forceinline__ float hadd2(u64 v) {
    float lo, hi;
    asm("mov.b64 {%0, %1}, %2;" : "=f"(lo), "=f"(hi) : "l"(v));
    return lo + hi;
}
__device__ __forceinline__ void lds_2u64(unsigned addr, u64& a, u64& b) {
    asm volatile("ld.shared.v2.u64 {%0, %1}, [%2];" : "=l"(a), "=l"(b) : "r"(addr));
}

__device__ __forceinline__ float sigmoid_f(float v) {
    return __fdividef(1.0f, 1.0f + __expf(-v));
}
__device__ __forceinline__ float tanh_f(float v) {
    return __fdividef(2.0f, 1.0f + __expf(-2.0f * v)) - 1.0f;
}

__global__ void __launch_bounds__(NTHREADS, 5)
lstm_kernel(const float* __restrict__ x,    // [T, B, 8]
            const float* __restrict__ Wih,  // [8, 80]
            const float* __restrict__ bih,  // [80]
            const float* __restrict__ Whh,  // [20, 80]
            const float* __restrict__ bhh,  // [80]
            const float* __restrict__ hx0,  // [1, 20]
            const float* __restrict__ cx0,  // [1, 20]
            float* __restrict__ out)        // [B, 20]
{
    __shared__ __align__(16) float sv[2][NGE][ROWW];

    const int tid = threadIdx.x;
    const bool active = (tid < GROUPS * HID);   // 60 of 64
    const int tc  = active ? tid : 0;
    const int g   = tc / HID;             // 0..2
    const int j   = tc % HID;             // 0..19
    const int b0  = blockIdx.x * NGE + g;
    const int b1  = b0 + GROUPS;
    const bool ok0 = active && (b0 < BATCH);
    const bool ok1 = active && (b1 < BATCH);
    const int cb0 = (b0 < BATCH) ? b0 : 0;
    const int cb1 = (b1 < BATCH) ? b1 : 0;

    // ---- k-pair-packed weights for unit j ----
    // whP[m][q] = (Whh[2m][colq], Whh[2m+1][colq]);  colq = q*HID + j
    u64 whP[HID / 2][4];
#pragma unroll
    for (int m = 0; m < HID / 2; m++)
#pragma unroll
        for (int q = 0; q < 4; q++)
            whP[m][q] = pack2(__ldg(&Whh[(2 * m) * G4 + q * HID + j]),
                              __ldg(&Whh[(2 * m + 1) * G4 + q * HID + j]));
    u64 wxP[INSZ / 2][4];
#pragma unroll
    for (int m = 0; m < INSZ / 2; m++)
#pragma unroll
        for (int q = 0; q < 4; q++)
            wxP[m][q] = pack2(__ldg(&Wih[(2 * m) * G4 + q * HID + j]),
                              __ldg(&Wih[(2 * m + 1) * G4 + q * HID + j]));
    u64 biasP[4];
#pragma unroll
    for (int q = 0; q < 4; q++)
        biasP[q] = pack2(__ldg(&bih[q * HID + j]) + __ldg(&bhh[q * HID + j]), 0.0f);

    float h0 = hx0[j], c0 = cx0[j];
    float h1 = h0,     c1 = c0;

    const float4* x4 = reinterpret_cast<const float4*>(x);
    // float4 index for (t, b, half): (t*BATCH + b)*2 + half

    // shared byte addresses of the two rows (buffer 0); buffer 1 = +BUFOFF
    const unsigned sbase = (unsigned)__cvta_generic_to_shared(&sv[0][0][0]);
    const unsigned BUFOFF = NGE * ROWW * 4u;
    const unsigned row0 = sbase + (unsigned)g * (ROWW * 4u);
    const unsigned row1 = sbase + (unsigned)(g + GROUPS) * (ROWW * 4u);

    // ---- prologue: xacc = bias + x_0 * W_ih (packed even/odd partials) ----
    u64 xacc0[4], xacc1[4];
    {
        const float4 a0 = x4[(0 * BATCH + cb0) * 2 + 0];
        const float4 a1 = x4[(0 * BATCH + cb0) * 2 + 1];
        const float4 e0 = x4[(0 * BATCH + cb1) * 2 + 0];
        const float4 e1 = x4[(0 * BATCH + cb1) * 2 + 1];
        const u64 xp0[4] = {pack2(a0.x, a0.y), pack2(a0.z, a0.w),
                            pack2(a1.x, a1.y), pack2(a1.z, a1.w)};
        const u64 xp1[4] = {pack2(e0.x, e0.y), pack2(e0.z, e0.w),
                            pack2(e1.x, e1.y), pack2(e1.z, e1.w)};
#pragma unroll
        for (int q = 0; q < 4; q++) {
            xacc0[q] = fma2(xp0[0], wxP[0][q], biasP[q]);
            xacc1[q] = fma2(xp1[0], wxP[0][q], biasP[q]);
        }
#pragma unroll
        for (int m = 1; m < INSZ / 2; m++)
#pragma unroll
            for (int q = 0; q < 4; q++) {
                xacc0[q] = fma2(xp0[m], wxP[m][q], xacc0[q]);
                xacc1[q] = fma2(xp1[m], wxP[m][q], xacc1[q]);
            }
    }

    if (active) {
        sv[0][g][j]          = h0;
        sv[0][g + GROUPS][j] = h1;
    }
    __syncthreads();

    unsigned curoff = 0;
#pragma unroll 2
    for (int t = 0; t < T_STEPS; t++) {
        const unsigned nxtoff = curoff ^ BUFOFF;

        // ---- issue x loads for step t+1 early (latency hidden by FMA block) ----
        const int tn = (t + 1 < T_STEPS) ? (t + 1) : t;
        const float4 xa0 = x4[((size_t)tn * BATCH + cb0) * 2 + 0];
        const float4 xa1 = x4[((size_t)tn * BATCH + cb0) * 2 + 1];
        const float4 xb0 = x4[((size_t)tn * BATCH + cb1) * 2 + 0];
        const float4 xb1 = x4[((size_t)tn * BATCH + cb1) * 2 + 1];

        // ---- gate sums: packed h·W_hh added onto precomputed x-part ----
        u64 A0[4], A1[4];
        {
            u64 pa, pb;
            lds_2u64(row0 + curoff, pa, pb);
#pragma unroll
            for (int q = 0; q < 4; q++) {
                A0[q] = fma2(pa, whP[0][q], xacc0[q]);
                A0[q] = fma2(pb, whP[1][q], A0[q]);
            }
            lds_2u64(row1 + curoff, pa, pb);
#pragma unroll
            for (int q = 0; q < 4; q++) {
                A1[q] = fma2(pa, whP[0][q], xacc1[q]);
                A1[q] = fma2(pb, whP[1][q], A1[q]);
            }
#pragma unroll
            for (int m = 1; m < 5; m++) {
                lds_2u64(row0 + curoff + 16u * m, pa, pb);
#pragma unroll
                for (int q = 0; q < 4; q++) {
                    A0[q] = fma2(pa, whP[2 * m][q], A0[q]);
                    A0[q] = fma2(pb, whP[2 * m + 1][q], A0[q]);
                }
                lds_2u64(row1 + curoff + 16u * m, pa, pb);
#pragma unroll
                for (int q = 0; q < 4; q++) {
                    A1[q] = fma2(pa, whP[2 * m][q], A1[q]);
                    A1[q] = fma2(pb, whP[2 * m + 1][q], A1[q]);
                }
            }
        }

        // ---- horizontal reduce + activations (MUFU-heavy) ----
        const float ii0 = sigmoid_f(hadd2(A0[0]));
        const float ff0 = sigmoid_f(hadd2(A0[1]));
        const float gg0 = tanh_f(hadd2(A0[2]));
        const float oo0 = sigmoid_f(hadd2(A0[3]));
        const float ii1 = sigmoid_f(hadd2(A1[0]));
        const float ff1 = sigmoid_f(hadd2(A1[1]));
        const float gg1 = tanh_f(hadd2(A1[2]));
        const float oo1 = sigmoid_f(hadd2(A1[3]));

        // ---- next step's x-projection: fills the MUFU shadow ----
        {
            const u64 xp0[4] = {pack2(xa0.x, xa0.y), pack2(xa0.z, xa0.w),
                                pack2(xa1.x, xa1.y), pack2(xa1.z, xa1.w)};
            const u64 xp1[4] = {pack2(xb0.x, xb0.y), pack2(xb0.z, xb0.w),
                                pack2(xb1.x, xb1.y), pack2(xb1.z, xb1.w)};
#pragma unroll
            for (int q = 0; q < 4; q++) {
                xacc0[q] = fma2(xp0[0], wxP[0][q], biasP[q]);
                xacc1[q] = fma2(xp1[0], wxP[0][q], biasP[q]);
            }
#pragma unroll
            for (int m = 1; m < INSZ / 2; m++)
#pragma unroll
                for (int q = 0; q < 4; q++) {
                    xacc0[q] = fma2(xp0[m], wxP[m][q], xacc0[q]);
                    xacc1[q] = fma2(xp1[m], wxP[m][q], xacc1[q]);
                }
        }

        // ---- state update ----
        c0 = ff0 * c0 + ii0 * gg0;
        c1 = ff1 * c1 + ii1 * gg1;
        h0 = oo0 * tanh_f(c0);
        h1 = oo1 * tanh_f(c1);

        if (t + 1 < T_STEPS) {
            if (active) {
                sv[0][0][0];  // no-op keep-alive (optimized out)
                *reinterpret_cast<float*>(
                    reinterpret_cast<char*>(&sv[0][0][0]) + (row0 - sbase) + nxtoff + 4u * j) = h0;
                *reinterpret_cast<float*>(
                    reinterpret_cast<char*>(&sv[0][0][0]) + (row1 - sbase) + nxtoff + 4u * j) = h1;
            }
            __syncthreads();
        }
        curoff = nxtoff;
    }

    if (ok0) out[b0 * HID + j] = h0;
    if (ok1) out[b1 * HID + j] = h1;
}

extern "C" void kernel_launch(void* const* d_in, const int* in_sizes, int n_in,
                              void* d_out, int out_size) {
    const float* x   = (const float*)d_in[0];
    const float* Wih = (const float*)d_in[1];
    const float* bih = (const float*)d_in[2];
    const float* Whh = (const float*)d_in[3];
    const float* bhh = (const float*)d_in[4];
    const float* hx0 = (const float*)d_in[5];
    const float* cx0 = (const float*)d_in[6];
    float* out = (float*)d_out;

    const int grid = (BATCH + NGE - 1) / NGE;  // 683
    lstm_kernel<<<grid, NTHREADS>>>(x, Wih, bih, Whh, bhh, hx0, cx0, out);
}